// round 7
// baseline (speedup 1.0000x reference)
#include <cuda_runtime.h>
#include <math.h>
#include <stdint.h>

// ---- problem constants (fixed shapes) ----
#define T_TOK  4096     // B * Q_LEN tokens
#define HIDDEN 4096
#define NH     32
#define HD     128
#define B_SEQ  8
#define Q_LEN  512
#define BS_PG  64       // paged-cache block size
#define NBLK   16

#define MAT_ELEMS ((size_t)4096 * 4096)

// ---- scratch (device globals; allocation-free) ----
__device__ float g_q[MAT_ELEMS];
__device__ float g_k[MAT_ELEMS];
__device__ float g_v[MAT_ELEMS];
__device__ float g_attn[MAT_ELEMS];   // written tf32-rounded by attn kernel
// tf32-pre-rounded GEMM operands
__device__ float g_hid_t[MAT_ELEMS];
__device__ float g_wq_t[MAT_ELEMS];
__device__ float g_wk_t[MAT_ELEMS];
__device__ float g_wv_t[MAT_ELEMS];
__device__ float g_wo_t[MAT_ELEMS];

// ---- helpers ----
__device__ __forceinline__ uint32_t smem_u32(const void* p) {
  return (uint32_t)__cvta_generic_to_shared(p);
}
__device__ __forceinline__ void cp_async16(uint32_t dst, const void* src) {
  asm volatile("cp.async.cg.shared.global [%0], [%1], 16;\n" ::"r"(dst), "l"(src));
}
__device__ __forceinline__ float f2tf_f(float x) {
  uint32_t u;
  asm("cvt.rna.tf32.f32 %0, %1;\n" : "=r"(u) : "f"(x));
  return __uint_as_float(u);
}
__device__ __forceinline__ void mma_tf32(float& d0, float& d1, float& d2, float& d3,
                                         uint32_t a0, uint32_t a1, uint32_t a2, uint32_t a3,
                                         uint32_t b0, uint32_t b1) {
  asm volatile(
      "mma.sync.aligned.m16n8k8.row.col.f32.tf32.tf32.f32 "
      "{%0,%1,%2,%3},{%4,%5,%6,%7},{%8,%9},{%0,%1,%2,%3};\n"
      : "+f"(d0), "+f"(d1), "+f"(d2), "+f"(d3)
      : "r"(a0), "r"(a1), "r"(a2), "r"(a3), "r"(b0), "r"(b1));
}

// ============================================================================
// Convert fp32 -> tf32 (rna), stored as float bits. Vectorized.
// ============================================================================
__global__ __launch_bounds__(256) void cvt_tf32_kernel(const float4* __restrict__ in,
                                                       float4* __restrict__ out) {
  size_t i = (size_t)blockIdx.x * 256 + threadIdx.x;
  if (i >= MAT_ELEMS / 4) return;
  float4 v = in[i];
  v.x = f2tf_f(v.x); v.y = f2tf_f(v.y); v.z = f2tf_f(v.z); v.w = f2tf_f(v.w);
  out[i] = v;
}

// ============================================================================
// TF32 tensor-core GEMM: C[4096,4096] = A @ B, operands PRE-ROUNDED to tf32.
// CTA tile 128x256, BK=16, 4-stage cp.async, 256 threads (8 warps 2m x 4n,
// warp tile 64x64, mma.m16n8k8 tf32). No in-loop CVT.
// ============================================================================
#define GBM 128
#define GBN 256
#define GBK 16
#define GSTAGES 4
#define GLDA 20                       // As row stride: conflict-free frag loads
#define GLDB 264                      // Bs row stride: conflict-free frag loads
#define AS_STAGE (GBM * GLDA)         // 2560 floats
#define BS_STAGE (GBK * GLDB)         // 4224 floats
#define STAGE_FLOATS (AS_STAGE + BS_STAGE)            // 6784
#define GEMM_SMEM_BYTES (STAGE_FLOATS * GSTAGES * 4)  // 108544 B

__device__ __forceinline__ void gemm_load_stage(
    float* smem, int s, int kt, int m0, int n0, int tid,
    const float* __restrict__ A, const float* __restrict__ B) {
  const int K = 4096, N = 4096;
  float* As = smem + s * STAGE_FLOATS;
  float* Bs = As + AS_STAGE;
  int k0 = kt * GBK;
  // A: 128 rows x 16 floats = 512 16B-chunks; 2 per thread
#pragma unroll
  for (int i = 0; i < 2; i++) {
    int c = tid + i * 256;
    int r = c >> 2, kc = (c & 3) * 4;
    cp_async16(smem_u32(As + r * GLDA + kc),
               A + (size_t)(m0 + r) * K + k0 + kc);
  }
  // B: 16 rows x 256 floats = 1024 16B-chunks; 4 per thread
#pragma unroll
  for (int i = 0; i < 4; i++) {
    int c = tid + i * 256;
    int kr = c >> 6, nc = (c & 63) * 4;
    cp_async16(smem_u32(Bs + kr * GLDB + nc),
               B + (size_t)(k0 + kr) * N + n0 + nc);
  }
}

__global__ __launch_bounds__(256, 1) void gemm_tf32(
    const float* __restrict__ A, const float* __restrict__ B,
    float* __restrict__ C) {
  extern __shared__ float smem[];
  const int K = 4096, N = 4096;
  int tid = threadIdx.x;
  int m0 = blockIdx.y * GBM, n0 = blockIdx.x * GBN;
  int lane = tid & 31, warp = tid >> 5;
  int g = lane >> 2, t = lane & 3;
  int wm = (warp & 1) * 64;   // 2 warps over 128 rows
  int wn = (warp >> 1) * 64;  // 4 warps over 256 cols

  float acc[4][8][4];
#pragma unroll
  for (int mi = 0; mi < 4; mi++)
#pragma unroll
    for (int ni = 0; ni < 8; ni++)
#pragma unroll
      for (int e = 0; e < 4; e++) acc[mi][ni][e] = 0.f;

  const int NT = K / GBK;  // 256
#pragma unroll
  for (int s = 0; s < GSTAGES - 1; s++) {
    gemm_load_stage(smem, s, s, m0, n0, tid, A, B);
    asm volatile("cp.async.commit_group;\n");
  }

  for (int kt = 0; kt < NT; kt++) {
    asm volatile("cp.async.wait_group %0;\n" ::"n"(GSTAGES - 2));
    __syncthreads();
    int pf = kt + GSTAGES - 1;
    if (pf < NT) gemm_load_stage(smem, pf % GSTAGES, pf, m0, n0, tid, A, B);
    asm volatile("cp.async.commit_group;\n");

    const float* As = smem + (kt % GSTAGES) * STAGE_FLOATS;
    const float* Bs = As + AS_STAGE;
#pragma unroll
    for (int kk = 0; kk < GBK; kk += 8) {
      uint32_t a[4][4], b[8][2];
#pragma unroll
      for (int mi = 0; mi < 4; mi++) {
        int r = wm + mi * 16 + g;
        a[mi][0] = __float_as_uint(As[r * GLDA + kk + t]);
        a[mi][1] = __float_as_uint(As[(r + 8) * GLDA + kk + t]);
        a[mi][2] = __float_as_uint(As[r * GLDA + kk + t + 4]);
        a[mi][3] = __float_as_uint(As[(r + 8) * GLDA + kk + t + 4]);
      }
#pragma unroll
      for (int ni = 0; ni < 8; ni++) {
        int c = wn + ni * 8 + g;
        b[ni][0] = __float_as_uint(Bs[(kk + t) * GLDB + c]);
        b[ni][1] = __float_as_uint(Bs[(kk + t + 4) * GLDB + c]);
      }
#pragma unroll
      for (int mi = 0; mi < 4; mi++)
#pragma unroll
        for (int ni = 0; ni < 8; ni++)
          mma_tf32(acc[mi][ni][0], acc[mi][ni][1], acc[mi][ni][2], acc[mi][ni][3],
                   a[mi][0], a[mi][1], a[mi][2], a[mi][3],
                   b[ni][0], b[ni][1]);
    }
  }

#pragma unroll
  for (int mi = 0; mi < 4; mi++) {
#pragma unroll
    for (int ni = 0; ni < 8; ni++) {
      int r = m0 + wm + mi * 16 + g;
      int c = n0 + wn + ni * 8 + 2 * t;
      *(float2*)(C + (size_t)r * N + c) =
          make_float2(acc[mi][ni][0], acc[mi][ni][1]);
      *(float2*)(C + (size_t)(r + 8) * N + c) =
          make_float2(acc[mi][ni][2], acc[mi][ni][3]);
    }
  }
}

// ============================================================================
// RoPE (in-place on g_q, g_k).
// ============================================================================
__global__ void rope_kernel(float* __restrict__ q, float* __restrict__ k,
                            const int* __restrict__ pos_ids) {
  int idx = blockIdx.x * 256 + threadIdx.x;
  if (idx >= T_TOK * NH * 64) return;
  int j = idx & 63;
  int th = idx >> 6;
  int t = th >> 5;
  float pos = (float)pos_ids[t];
  float inv = expf(-logf(10000.f) * (float)(2 * j) * (1.f / 128.f));
  float ang = pos * inv;
  float s, c;
  sincosf(ang, &s, &c);
  size_t base = (size_t)th * 128;
  float q1 = q[base + j], q2 = q[base + j + 64];
  q[base + j]      = q1 * c - q2 * s;
  q[base + j + 64] = q2 * c + q1 * s;
  float k1 = k[base + j], k2 = k[base + j + 64];
  k[base + j]      = k1 * c - k2 * s;
  k[base + j + 64] = k2 * c + k1 * s;
}

// ============================================================================
// Flash attention, fp32 math, cp.async double-buffered K/V, float4 QK loads.
// One CTA per (q-tile of 64, head, seq). Output written tf32-rounded.
// ============================================================================
#define LDQ 132
#define LDK 132
#define LDV 128
#define LDSS 65
#define OFF_Q 0
#define KBUF_STRIDE (64 * LDK)            // 8448
#define OFF_K 8448                        // 2 buffers
#define VBUF_STRIDE (64 * LDV)            // 8192
#define OFF_V (OFF_K + 2 * KBUF_STRIDE)   // 25344
#define OFF_S (OFF_V + 2 * VBUF_STRIDE)   // 41728
#define OFF_M (OFF_S + 64 * LDSS)         // 45888
#define OFF_L (OFF_M + 64)
#define OFF_A (OFF_L + 64)
#define OFF_P (OFF_A + 64)
#define ATTN_SMEM_FLOATS (OFF_P + 64)     // 46144 -> 184576 B

__device__ __forceinline__ void attn_load_tile(
    float* Ks, float* Vs, int kt, int b, int h, int tid,
    const float* __restrict__ k_cache, const float* __restrict__ v_cache,
    const int* __restrict__ block_tab) {
  const float *kbase, *vbase;
  if (kt < 8) {
    int blk = block_tab[b * NBLK + kt];
    size_t off = ((size_t)blk * BS_PG * NH + h) * HD;
    kbase = k_cache + off;
    vbase = v_cache + off;
  } else {
    size_t off = (size_t)(b * Q_LEN + (kt - 8) * 64) * HIDDEN + h * HD;
    kbase = g_k + off;
    vbase = g_v + off;
  }
#pragma unroll
  for (int j = 0; j < 8; j++) {
    int i = tid + j * 256;
    int r = i >> 5, d4 = (i & 31) * 4;
    cp_async16(smem_u32(Ks + r * LDK + d4), kbase + (size_t)r * HIDDEN + d4);
    cp_async16(smem_u32(Vs + r * LDV + d4), vbase + (size_t)r * HIDDEN + d4);
  }
}

__global__ __launch_bounds__(256, 1) void attn_kernel(
    const float* __restrict__ k_cache, const float* __restrict__ v_cache,
    const int* __restrict__ block_tab, const int* __restrict__ pos_ids,
    const int* __restrict__ kv_len) {
  extern __shared__ float sm[];
  float* Qs = sm + OFF_Q;
  float* Ss = sm + OFF_S;
  float* Ms = sm + OFF_M;
  float* Ls = sm + OFF_L;
  float* Al = sm + OFF_A;
  int* Ps = (int*)(sm + OFF_P);

  int qt = blockIdx.x, h = blockIdx.y, b = blockIdx.z;
  int tid = threadIdx.x;
  int tr = tid >> 4, tc = tid & 15;
  int t_base = b * Q_LEN + qt * 64;

  // Q tile [64 x 128]
  for (int i = tid; i < 64 * 32; i += 256) {
    int r = i >> 5, d4 = (i & 31) * 4;
    float4 v = *(const float4*)(g_q + (size_t)(t_base + r) * HIDDEN + h * HD + d4);
    *(float4*)(&Qs[r * LDQ + d4]) = v;
  }
  if (tid < 64) {
    Ps[tid] = pos_ids[t_base + tid];
    Ms[tid] = -1e30f;
    Ls[tid] = 0.f;
  }

  int kvl = kv_len[b];
  int nt = min(qt + 9, 16);  // causal: tiles 0..(8+qt); clamp
  {
    int full = (kvl + 63) / 64;
    if (nt > full) nt = full;
  }

  // prefetch tile 0
  attn_load_tile(sm + OFF_K, sm + OFF_V, 0, b, h, tid, k_cache, v_cache, block_tab);
  asm volatile("cp.async.commit_group;\n");

  float acc[4][8];
#pragma unroll
  for (int i = 0; i < 4; i++)
#pragma unroll
    for (int j = 0; j < 8; j++) acc[i][j] = 0.f;

  const float scale = 0.08838834764831845f;  // 1/sqrt(128)

  for (int kt = 0; kt < nt; kt++) {
    if (kt + 1 < nt) {
      attn_load_tile(sm + OFF_K + ((kt + 1) & 1) * KBUF_STRIDE,
                     sm + OFF_V + ((kt + 1) & 1) * VBUF_STRIDE,
                     kt + 1, b, h, tid, k_cache, v_cache, block_tab);
      asm volatile("cp.async.commit_group;\n");
      asm volatile("cp.async.wait_group 1;\n");
    } else {
      asm volatile("cp.async.wait_group 0;\n");
    }
    __syncthreads();

    const float* Ks = sm + OFF_K + (kt & 1) * KBUF_STRIDE;
    const float* Vs = sm + OFF_V + (kt & 1) * VBUF_STRIDE;

    // ---- S = Q K^T (64x64), 4x4 micro-tile, float4 over d ----
    float accs[4][4];
#pragma unroll
    for (int i = 0; i < 4; i++)
#pragma unroll
      for (int j = 0; j < 4; j++) accs[i][j] = 0.f;
#pragma unroll 2
    for (int d = 0; d < 128; d += 4) {
      float4 qa[4], kb[4];
#pragma unroll
      for (int i = 0; i < 4; i++)
        qa[i] = *(const float4*)(&Qs[(tr * 4 + i) * LDQ + d]);
#pragma unroll
      for (int j = 0; j < 4; j++)
        kb[j] = *(const float4*)(&Ks[(tc * 4 + j) * LDK + d]);
#pragma unroll
      for (int i = 0; i < 4; i++)
#pragma unroll
        for (int j = 0; j < 4; j++) {
          accs[i][j] = fmaf(qa[i].x, kb[j].x, accs[i][j]);
          accs[i][j] = fmaf(qa[i].y, kb[j].y, accs[i][j]);
          accs[i][j] = fmaf(qa[i].z, kb[j].z, accs[i][j]);
          accs[i][j] = fmaf(qa[i].w, kb[j].w, accs[i][j]);
        }
    }
#pragma unroll
    for (int i = 0; i < 4; i++) {
      int r = tr * 4 + i;
      int qp = Ps[r];
#pragma unroll
      for (int j = 0; j < 4; j++) {
        int kvp = kt * 64 + tc * 4 + j;
        float sv = accs[i][j] * scale;
        if (kvp > qp || kvp >= kvl) sv = -1e30f;
        Ss[r * LDSS + tc * 4 + j] = sv;
      }
    }
    __syncthreads();

    // ---- online softmax row update: 4 threads per row ----
    {
      int row = tid >> 2, q4 = tid & 3;
      float mx = -1e30f;
#pragma unroll
      for (int i = 0; i < 16; i++) mx = fmaxf(mx, Ss[row * LDSS + q4 * 16 + i]);
      mx = fmaxf(mx, __shfl_xor_sync(0xffffffffu, mx, 1));
      mx = fmaxf(mx, __shfl_xor_sync(0xffffffffu, mx, 2));
      float m_old = Ms[row];
      float m_new = fmaxf(m_old, mx);
      float sum = 0.f;
#pragma unroll
      for (int i = 0; i < 16; i++) {
        float p = __expf(Ss[row * LDSS + q4 * 16 + i] - m_new);
        Ss[row * LDSS + q4 * 16 + i] = p;
        sum += p;
      }
      sum += __shfl_xor_sync(0xffffffffu, sum, 1);
      sum += __shfl_xor_sync(0xffffffffu, sum, 2);
      if (q4 == 0) {
        float alpha = __expf(m_old - m_new);
        Al[row] = alpha;
        Ls[row] = Ls[row] * alpha + sum;
        Ms[row] = m_new;
      }
    }
    __syncthreads();

    // ---- rescale acc, then O += P @ V ----
#pragma unroll
    for (int i = 0; i < 4; i++) {
      float a = Al[tr * 4 + i];
#pragma unroll
      for (int j = 0; j < 8; j++) acc[i][j] *= a;
    }
#pragma unroll 2
    for (int kk = 0; kk < 64; kk++) {
      float rp[4];
#pragma unroll
      for (int i = 0; i < 4; i++) rp[i] = Ss[(tr * 4 + i) * LDSS + kk];
      float4 v0 = *(const float4*)(&Vs[kk * LDV + tc * 8]);
      float4 v1 = *(const float4*)(&Vs[kk * LDV + tc * 8 + 4]);
      float rv[8] = {v0.x, v0.y, v0.z, v0.w, v1.x, v1.y, v1.z, v1.w};
#pragma unroll
      for (int i = 0; i < 4; i++)
#pragma unroll
        for (int j = 0; j < 8; j++)
          acc[i][j] = fmaf(rp[i], rv[j], acc[i][j]);
    }
    __syncthreads();
  }

  // ---- normalize + tf32-round + write ----
#pragma unroll
  for (int i = 0; i < 4; i++) {
    int r = tr * 4 + i;
    float inv_l = 1.f / Ls[r];
    float* dst = g_attn + (size_t)(t_base + r) * HIDDEN + h * HD + tc * 8;
    float4 o0 = make_float4(f2tf_f(acc[i][0] * inv_l), f2tf_f(acc[i][1] * inv_l),
                            f2tf_f(acc[i][2] * inv_l), f2tf_f(acc[i][3] * inv_l));
    float4 o1 = make_float4(f2tf_f(acc[i][4] * inv_l), f2tf_f(acc[i][5] * inv_l),
                            f2tf_f(acc[i][6] * inv_l), f2tf_f(acc[i][7] * inv_l));
    *(float4*)(dst) = o0;
    *(float4*)(dst + 4) = o1;
  }
}

// ============================================================================
extern "C" void kernel_launch(void* const* d_in, const int* in_sizes, int n_in,
                              void* d_out, int out_size) {
  const float* hidden = (const float*)d_in[0];
  const float* Wq = (const float*)d_in[1];
  const float* Wk = (const float*)d_in[2];
  const float* Wv = (const float*)d_in[3];
  const float* Wo = (const float*)d_in[4];
  const float* kc = (const float*)d_in[5];
  const float* vc = (const float*)d_in[6];
  const int* btab = (const int*)d_in[7];
  const int* pos = (const int*)d_in[8];
  const int* kvlen = (const int*)d_in[9];
  float* out = (float*)d_out;

  float *q, *k, *v, *attn, *hid_t, *wq_t, *wk_t, *wv_t, *wo_t;
  cudaGetSymbolAddress((void**)&q, g_q);
  cudaGetSymbolAddress((void**)&k, g_k);
  cudaGetSymbolAddress((void**)&v, g_v);
  cudaGetSymbolAddress((void**)&attn, g_attn);
  cudaGetSymbolAddress((void**)&hid_t, g_hid_t);
  cudaGetSymbolAddress((void**)&wq_t, g_wq_t);
  cudaGetSymbolAddress((void**)&wk_t, g_wk_t);
  cudaGetSymbolAddress((void**)&wv_t, g_wv_t);
  cudaGetSymbolAddress((void**)&wo_t, g_wo_t);

  // pre-round GEMM operands to tf32
  int cvt_grid = (int)((MAT_ELEMS / 4 + 255) / 256);
  cvt_tf32_kernel<<<cvt_grid, 256>>>((const float4*)hidden, (float4*)hid_t);
  cvt_tf32_kernel<<<cvt_grid, 256>>>((const float4*)Wq, (float4*)wq_t);
  cvt_tf32_kernel<<<cvt_grid, 256>>>((const float4*)Wk, (float4*)wk_t);
  cvt_tf32_kernel<<<cvt_grid, 256>>>((const float4*)Wv, (float4*)wv_t);
  cvt_tf32_kernel<<<cvt_grid, 256>>>((const float4*)Wo, (float4*)wo_t);

  cudaFuncSetAttribute(gemm_tf32, cudaFuncAttributeMaxDynamicSharedMemorySize,
                       GEMM_SMEM_BYTES);
  dim3 gg(16, 32);  // N/256, M/128
  gemm_tf32<<<gg, 256, GEMM_SMEM_BYTES>>>(hid_t, wq_t, q);
  gemm_tf32<<<gg, 256, GEMM_SMEM_BYTES>>>(hid_t, wk_t, k);
  gemm_tf32<<<gg, 256, GEMM_SMEM_BYTES>>>(hid_t, wv_t, v);

  rope_kernel<<<(T_TOK * NH * 64 + 255) / 256, 256>>>(q, k, pos);

  cudaFuncSetAttribute(attn_kernel, cudaFuncAttributeMaxDynamicSharedMemorySize,
                       ATTN_SMEM_FLOATS * 4);
  dim3 ga(8, NH, B_SEQ);  // (q-tile, head, seq)
  attn_kernel<<<ga, 256, ATTN_SMEM_FLOATS * 4>>>(kc, vc, btab, pos, kvlen);

  gemm_tf32<<<gg, 256, GEMM_SMEM_BYTES>>>(attn, wo_t, out);
}

// round 8
// speedup vs baseline: 1.1684x; 1.1684x over previous
#include <cuda_runtime.h>
#include <math.h>
#include <stdint.h>

// ---- problem constants (fixed shapes) ----
#define T_TOK  4096     // B * Q_LEN tokens
#define HIDDEN 4096
#define NH     32
#define HD     128
#define B_SEQ  8
#define Q_LEN  512
#define BS_PG  64       // paged-cache block size
#define NBLK   16

#define MAT_ELEMS ((size_t)4096 * 4096)

// ---- scratch (device globals; allocation-free) ----
__device__ float g_q[MAT_ELEMS];
__device__ float g_k[MAT_ELEMS];
__device__ float g_v[MAT_ELEMS];
__device__ float g_attn[MAT_ELEMS];   // written tf32-rounded by attn kernel
// tf32-pre-rounded GEMM operands
__device__ float g_hid_t[MAT_ELEMS];
__device__ float g_wq_t[MAT_ELEMS];
__device__ float g_wk_t[MAT_ELEMS];
__device__ float g_wv_t[MAT_ELEMS];
__device__ float g_wo_t[MAT_ELEMS];

// ---- helpers ----
__device__ __forceinline__ uint32_t smem_u32(const void* p) {
  return (uint32_t)__cvta_generic_to_shared(p);
}
__device__ __forceinline__ void cp_async16(uint32_t dst, const void* src) {
  asm volatile("cp.async.cg.shared.global [%0], [%1], 16;\n" ::"r"(dst), "l"(src));
}
__device__ __forceinline__ float f2tf_f(float x) {
  uint32_t u;
  asm("cvt.rna.tf32.f32 %0, %1;\n" : "=r"(u) : "f"(x));
  return __uint_as_float(u);
}
__device__ __forceinline__ void mma_tf32(float& d0, float& d1, float& d2, float& d3,
                                         uint32_t a0, uint32_t a1, uint32_t a2, uint32_t a3,
                                         uint32_t b0, uint32_t b1) {
  asm volatile(
      "mma.sync.aligned.m16n8k8.row.col.f32.tf32.tf32.f32 "
      "{%0,%1,%2,%3},{%4,%5,%6,%7},{%8,%9},{%0,%1,%2,%3};\n"
      : "+f"(d0), "+f"(d1), "+f"(d2), "+f"(d3)
      : "r"(a0), "r"(a1), "r"(a2), "r"(a3), "r"(b0), "r"(b1));
}

// ============================================================================
// Convert fp32 -> tf32 (rna), stored as float bits. Vectorized.
// ============================================================================
__global__ __launch_bounds__(256) void cvt_tf32_kernel(const float4* __restrict__ in,
                                                       float4* __restrict__ out) {
  size_t i = (size_t)blockIdx.x * 256 + threadIdx.x;
  if (i >= MAT_ELEMS / 4) return;
  float4 v = in[i];
  v.x = f2tf_f(v.x); v.y = f2tf_f(v.y); v.z = f2tf_f(v.z); v.w = f2tf_f(v.w);
  out[i] = v;
}

// ============================================================================
// TF32 tensor-core GEMM (R4 proven config): C = A @ B, operands PRE-ROUNDED.
// CTA tile 128x128, BK=16, 4-stage cp.async, 256 threads (8 warps 2m x 4n,
// warp tile 64x32, mma.m16n8k8). No in-loop CVT.
// ============================================================================
#define GBM 128
#define GBN 128
#define GBK 16
#define GSTAGES 4
#define GLDA 20
#define GLDB 136
#define AS_STAGE (GBM * GLDA)         // 2560 floats
#define BS_STAGE (GBK * GLDB)         // 2176 floats
#define STAGE_FLOATS (AS_STAGE + BS_STAGE)            // 4736
#define GEMM_SMEM_BYTES (STAGE_FLOATS * GSTAGES * 4)  // 75776 B

__device__ __forceinline__ void gemm_load_stage(
    float* smem, int s, int kt, int m0, int n0, int tid,
    const float* __restrict__ A, const float* __restrict__ B) {
  const int K = 4096, N = 4096;
  float* As = smem + s * STAGE_FLOATS;
  float* Bs = As + AS_STAGE;
  int k0 = kt * GBK;
#pragma unroll
  for (int i = 0; i < 2; i++) {
    int c = tid + i * 256;
    int r = c >> 2, kc = (c & 3) * 4;
    cp_async16(smem_u32(As + r * GLDA + kc),
               A + (size_t)(m0 + r) * K + k0 + kc);
  }
#pragma unroll
  for (int i = 0; i < 2; i++) {
    int c = tid + i * 256;
    int kr = c >> 5, nc = (c & 31) * 4;
    cp_async16(smem_u32(Bs + kr * GLDB + nc),
               B + (size_t)(k0 + kr) * N + n0 + nc);
  }
}

__global__ __launch_bounds__(256, 1) void gemm_tf32(
    const float* __restrict__ A, const float* __restrict__ B,
    float* __restrict__ C) {
  extern __shared__ float smem[];
  const int K = 4096, N = 4096;
  int tid = threadIdx.x;
  int m0 = blockIdx.y * GBM, n0 = blockIdx.x * GBN;
  int lane = tid & 31, warp = tid >> 5;
  int g = lane >> 2, t = lane & 3;
  int wm = (warp & 1) * 64;
  int wn = (warp >> 1) * 32;

  float acc[4][4][4];
#pragma unroll
  for (int mi = 0; mi < 4; mi++)
#pragma unroll
    for (int ni = 0; ni < 4; ni++)
#pragma unroll
      for (int e = 0; e < 4; e++) acc[mi][ni][e] = 0.f;

  const int NT = K / GBK;  // 256
#pragma unroll
  for (int s = 0; s < GSTAGES - 1; s++) {
    gemm_load_stage(smem, s, s, m0, n0, tid, A, B);
    asm volatile("cp.async.commit_group;\n");
  }

  for (int kt = 0; kt < NT; kt++) {
    asm volatile("cp.async.wait_group %0;\n" ::"n"(GSTAGES - 2));
    __syncthreads();
    int pf = kt + GSTAGES - 1;
    if (pf < NT) gemm_load_stage(smem, pf % GSTAGES, pf, m0, n0, tid, A, B);
    asm volatile("cp.async.commit_group;\n");

    const float* As = smem + (kt % GSTAGES) * STAGE_FLOATS;
    const float* Bs = As + AS_STAGE;
#pragma unroll
    for (int kk = 0; kk < GBK; kk += 8) {
      uint32_t a[4][4], b[4][2];
#pragma unroll
      for (int mi = 0; mi < 4; mi++) {
        int r = wm + mi * 16 + g;
        a[mi][0] = __float_as_uint(As[r * GLDA + kk + t]);
        a[mi][1] = __float_as_uint(As[(r + 8) * GLDA + kk + t]);
        a[mi][2] = __float_as_uint(As[r * GLDA + kk + t + 4]);
        a[mi][3] = __float_as_uint(As[(r + 8) * GLDA + kk + t + 4]);
      }
#pragma unroll
      for (int ni = 0; ni < 4; ni++) {
        int c = wn + ni * 8 + g;
        b[ni][0] = __float_as_uint(Bs[(kk + t) * GLDB + c]);
        b[ni][1] = __float_as_uint(Bs[(kk + t + 4) * GLDB + c]);
      }
#pragma unroll
      for (int mi = 0; mi < 4; mi++)
#pragma unroll
        for (int ni = 0; ni < 4; ni++)
          mma_tf32(acc[mi][ni][0], acc[mi][ni][1], acc[mi][ni][2], acc[mi][ni][3],
                   a[mi][0], a[mi][1], a[mi][2], a[mi][3],
                   b[ni][0], b[ni][1]);
    }
  }

#pragma unroll
  for (int mi = 0; mi < 4; mi++) {
#pragma unroll
    for (int ni = 0; ni < 4; ni++) {
      int r = m0 + wm + mi * 16 + g;
      int c = n0 + wn + ni * 8 + 2 * t;
      *(float2*)(C + (size_t)r * N + c) =
          make_float2(acc[mi][ni][0], acc[mi][ni][1]);
      *(float2*)(C + (size_t)(r + 8) * N + c) =
          make_float2(acc[mi][ni][2], acc[mi][ni][3]);
    }
  }
}

// ============================================================================
// RoPE (in-place on g_q, g_k).
// ============================================================================
__global__ void rope_kernel(float* __restrict__ q, float* __restrict__ k,
                            const int* __restrict__ pos_ids) {
  int idx = blockIdx.x * 256 + threadIdx.x;
  if (idx >= T_TOK * NH * 64) return;
  int j = idx & 63;
  int th = idx >> 6;
  int t = th >> 5;
  float pos = (float)pos_ids[t];
  float inv = expf(-logf(10000.f) * (float)(2 * j) * (1.f / 128.f));
  float ang = pos * inv;
  float s, c;
  sincosf(ang, &s, &c);
  size_t base = (size_t)th * 128;
  float q1 = q[base + j], q2 = q[base + j + 64];
  q[base + j]      = q1 * c - q2 * s;
  q[base + j + 64] = q2 * c + q1 * s;
  float k1 = k[base + j], k2 = k[base + j + 64];
  k[base + j]      = k1 * c - k2 * s;
  k[base + j + 64] = k2 * c + k1 * s;
}

// ============================================================================
// Flash attention, fp32, high arithmetic intensity.
// CTA = (q-tile 128, head, seq); KV tile 128 (2 cache pages).
// 16x16 thread grid, 8x8 micro-tiles. S staged via K smem region (aliased).
// QK column ownership interleaved (c = tc + 16j) for conflict-free K LDS.
// Softmax state (m,l) in registers; 16-lane shfl row reductions.
// ============================================================================
#define ALDQ 132
#define ALDK 132                         // also S stride
#define ALDV 128
#define AOFF_K (128 * ALDQ)              // 16896
#define AOFF_V (AOFF_K + 128 * ALDK)     // 33792
#define AOFF_P (AOFF_V + 128 * ALDV)     // 50176
#define ATTN_SMEM_FLOATS (AOFF_P + 128)  // 50304 -> 201216 B

__global__ __launch_bounds__(256, 1) void attn_kernel(
    const float* __restrict__ k_cache, const float* __restrict__ v_cache,
    const int* __restrict__ block_tab, const int* __restrict__ pos_ids,
    const int* __restrict__ kv_len) {
  extern __shared__ float sm[];
  float* Qs = sm;
  float* Ks = sm + AOFF_K;   // aliased by S after QK
  float* Vs = sm + AOFF_V;
  int* Ps = (int*)(sm + AOFF_P);

  int qt = blockIdx.x, h = blockIdx.y, b = blockIdx.z;
  int tid = threadIdx.x;
  int tr = tid >> 4, tc = tid & 15;
  int t_base = b * Q_LEN + qt * 128;

  // ---- Q tile [128 x 128] ----
  for (int i = tid; i < 128 * 32; i += 256) {
    int r = i >> 5, d4 = (i & 31) * 4;
    float4 v = *(const float4*)(g_q + (size_t)(t_base + r) * HIDDEN + h * HD + d4);
    *(float4*)(&Qs[r * ALDQ + d4]) = v;
  }
  if (tid < 128) Ps[tid] = pos_ids[t_base + tid];
  __syncthreads();

  int kvl = kv_len[b];
  int maxp = 0;
  for (int i = 0; i < 128; i++) maxp = max(maxp, Ps[i]);
  int nt = min(maxp / 128 + 1, (kvl + 127) / 128);
  if (nt > 8) nt = 8;

  float m[8], l[8], o[8][8];
#pragma unroll
  for (int i = 0; i < 8; i++) {
    m[i] = -1e30f;
    l[i] = 0.f;
#pragma unroll
    for (int j = 0; j < 8; j++) o[i][j] = 0.f;
  }

  const float scale = 0.08838834764831845f;  // 1/sqrt(128)
  int qp_[8];
#pragma unroll
  for (int i = 0; i < 8; i++) qp_[i] = Ps[tr * 8 + i];

  for (int kt = 0; kt < nt; kt++) {
    __syncthreads();  // prior PV readers of Ss/Vs done before overwrite

    // ---- load K/V tile [128 x 128] via cp.async ----
    int blk0 = 0, blk1 = 0;
    if (kt < 4) {
      blk0 = block_tab[b * NBLK + 2 * kt];
      blk1 = block_tab[b * NBLK + 2 * kt + 1];
    }
#pragma unroll
    for (int j = 0; j < 16; j++) {
      int i = tid + j * 256;
      int r = i >> 5, d4 = (i & 31) * 4;
      const float *kb, *vb;
      if (kt < 4) {
        int blk = (r < 64) ? blk0 : blk1;
        size_t off = ((size_t)(blk * BS_PG + (r & 63)) * NH + h) * HD + d4;
        kb = k_cache + off;
        vb = v_cache + off;
      } else {
        size_t off = (size_t)(b * Q_LEN + (kt - 4) * 128 + r) * HIDDEN + h * HD + d4;
        kb = g_k + off;
        vb = g_v + off;
      }
      cp_async16(smem_u32(Ks + r * ALDK + d4), kb);
      cp_async16(smem_u32(Vs + r * ALDV + d4), vb);
    }
    asm volatile("cp.async.commit_group;\n");
    asm volatile("cp.async.wait_group 0;\n");
    __syncthreads();

    // ---- S = Q K^T : rows tr*8+i, cols tc + 16j ----
    float s_[8][8];
#pragma unroll
    for (int i = 0; i < 8; i++)
#pragma unroll
      for (int j = 0; j < 8; j++) s_[i][j] = 0.f;
#pragma unroll 4
    for (int d = 0; d < 128; d += 2) {
      float2 qa[8], kb[8];
#pragma unroll
      for (int i = 0; i < 8; i++)
        qa[i] = *(const float2*)(&Qs[(tr * 8 + i) * ALDQ + d]);
#pragma unroll
      for (int j = 0; j < 8; j++)
        kb[j] = *(const float2*)(&Ks[(tc + 16 * j) * ALDK + d]);
#pragma unroll
      for (int i = 0; i < 8; i++)
#pragma unroll
        for (int j = 0; j < 8; j++) {
          s_[i][j] = fmaf(qa[i].x, kb[j].x, s_[i][j]);
          s_[i][j] = fmaf(qa[i].y, kb[j].y, s_[i][j]);
        }
    }
    __syncthreads();  // all K reads done; Ks region now reusable for S

    // ---- mask + online softmax (registers + 16-lane shfl) ----
#pragma unroll
    for (int i = 0; i < 8; i++) {
      int qp = qp_[i];
      float rmax = -1e30f;
#pragma unroll
      for (int j = 0; j < 8; j++) {
        int kvp = kt * 128 + tc + 16 * j;
        float sv = s_[i][j] * scale;
        if (kvp > qp || kvp >= kvl) sv = -1e30f;
        s_[i][j] = sv;
        rmax = fmaxf(rmax, sv);
      }
      rmax = fmaxf(rmax, __shfl_xor_sync(0xffffffffu, rmax, 1));
      rmax = fmaxf(rmax, __shfl_xor_sync(0xffffffffu, rmax, 2));
      rmax = fmaxf(rmax, __shfl_xor_sync(0xffffffffu, rmax, 4));
      rmax = fmaxf(rmax, __shfl_xor_sync(0xffffffffu, rmax, 8));
      float mnew = fmaxf(m[i], rmax);
      float sum = 0.f;
#pragma unroll
      for (int j = 0; j < 8; j++) {
        float p = __expf(s_[i][j] - mnew);
        s_[i][j] = p;
        sum += p;
      }
      sum += __shfl_xor_sync(0xffffffffu, sum, 1);
      sum += __shfl_xor_sync(0xffffffffu, sum, 2);
      sum += __shfl_xor_sync(0xffffffffu, sum, 4);
      sum += __shfl_xor_sync(0xffffffffu, sum, 8);
      float alpha = __expf(m[i] - mnew);
      m[i] = mnew;
      l[i] = l[i] * alpha + sum;
#pragma unroll
      for (int j = 0; j < 8; j++) o[i][j] *= alpha;
    }

    // ---- stage P into smem (K region) ----
    float* Ss = Ks;
#pragma unroll
    for (int i = 0; i < 8; i++)
#pragma unroll
      for (int j = 0; j < 8; j++)
        Ss[(tr * 8 + i) * ALDK + tc + 16 * j] = s_[i][j];
    __syncthreads();

    // ---- O += P @ V : O cols tc*8..tc*8+7 ----
#pragma unroll 2
    for (int kk = 0; kk < 128; kk++) {
      float rp[8];
#pragma unroll
      for (int i = 0; i < 8; i++) rp[i] = Ss[(tr * 8 + i) * ALDK + kk];
      float4 v0 = *(const float4*)(&Vs[kk * ALDV + tc * 8]);
      float4 v1 = *(const float4*)(&Vs[kk * ALDV + tc * 8 + 4]);
#pragma unroll
      for (int i = 0; i < 8; i++) {
        o[i][0] = fmaf(rp[i], v0.x, o[i][0]);
        o[i][1] = fmaf(rp[i], v0.y, o[i][1]);
        o[i][2] = fmaf(rp[i], v0.z, o[i][2]);
        o[i][3] = fmaf(rp[i], v0.w, o[i][3]);
        o[i][4] = fmaf(rp[i], v1.x, o[i][4]);
        o[i][5] = fmaf(rp[i], v1.y, o[i][5]);
        o[i][6] = fmaf(rp[i], v1.z, o[i][6]);
        o[i][7] = fmaf(rp[i], v1.w, o[i][7]);
      }
    }
  }

  // ---- normalize + tf32-round + write ----
#pragma unroll
  for (int i = 0; i < 8; i++) {
    int r = tr * 8 + i;
    float inv_l = 1.f / l[i];
    float* dst = g_attn + (size_t)(t_base + r) * HIDDEN + h * HD + tc * 8;
    float4 o0 = make_float4(f2tf_f(o[i][0] * inv_l), f2tf_f(o[i][1] * inv_l),
                            f2tf_f(o[i][2] * inv_l), f2tf_f(o[i][3] * inv_l));
    float4 o1 = make_float4(f2tf_f(o[i][4] * inv_l), f2tf_f(o[i][5] * inv_l),
                            f2tf_f(o[i][6] * inv_l), f2tf_f(o[i][7] * inv_l));
    *(float4*)(dst) = o0;
    *(float4*)(dst + 4) = o1;
  }
}

// ============================================================================
extern "C" void kernel_launch(void* const* d_in, const int* in_sizes, int n_in,
                              void* d_out, int out_size) {
  const float* hidden = (const float*)d_in[0];
  const float* Wq = (const float*)d_in[1];
  const float* Wk = (const float*)d_in[2];
  const float* Wv = (const float*)d_in[3];
  const float* Wo = (const float*)d_in[4];
  const float* kc = (const float*)d_in[5];
  const float* vc = (const float*)d_in[6];
  const int* btab = (const int*)d_in[7];
  const int* pos = (const int*)d_in[8];
  const int* kvlen = (const int*)d_in[9];
  float* out = (float*)d_out;

  float *q, *k, *v, *attn, *hid_t, *wq_t, *wk_t, *wv_t, *wo_t;
  cudaGetSymbolAddress((void**)&q, g_q);
  cudaGetSymbolAddress((void**)&k, g_k);
  cudaGetSymbolAddress((void**)&v, g_v);
  cudaGetSymbolAddress((void**)&attn, g_attn);
  cudaGetSymbolAddress((void**)&hid_t, g_hid_t);
  cudaGetSymbolAddress((void**)&wq_t, g_wq_t);
  cudaGetSymbolAddress((void**)&wk_t, g_wk_t);
  cudaGetSymbolAddress((void**)&wv_t, g_wv_t);
  cudaGetSymbolAddress((void**)&wo_t, g_wo_t);

  // pre-round GEMM operands to tf32
  int cvt_grid = (int)((MAT_ELEMS / 4 + 255) / 256);
  cvt_tf32_kernel<<<cvt_grid, 256>>>((const float4*)hidden, (float4*)hid_t);
  cvt_tf32_kernel<<<cvt_grid, 256>>>((const float4*)Wq, (float4*)wq_t);
  cvt_tf32_kernel<<<cvt_grid, 256>>>((const float4*)Wk, (float4*)wk_t);
  cvt_tf32_kernel<<<cvt_grid, 256>>>((const float4*)Wv, (float4*)wv_t);
  cvt_tf32_kernel<<<cvt_grid, 256>>>((const float4*)Wo, (float4*)wo_t);

  cudaFuncSetAttribute(gemm_tf32, cudaFuncAttributeMaxDynamicSharedMemorySize,
                       GEMM_SMEM_BYTES);
  dim3 gg(32, 32);  // N/128, M/128
  gemm_tf32<<<gg, 256, GEMM_SMEM_BYTES>>>(hid_t, wq_t, q);
  gemm_tf32<<<gg, 256, GEMM_SMEM_BYTES>>>(hid_t, wk_t, k);
  gemm_tf32<<<gg, 256, GEMM_SMEM_BYTES>>>(hid_t, wv_t, v);

  rope_kernel<<<(T_TOK * NH * 64 + 255) / 256, 256>>>(q, k, pos);

  cudaFuncSetAttribute(attn_kernel, cudaFuncAttributeMaxDynamicSharedMemorySize,
                       ATTN_SMEM_FLOATS * 4);
  dim3 ga(4, NH, B_SEQ);  // (q-tile of 128, head, seq)
  attn_kernel<<<ga, 256, ATTN_SMEM_FLOATS * 4>>>(kc, vc, btab, pos, kvlen);

  gemm_tf32<<<gg, 256, GEMM_SMEM_BYTES>>>(attn, wo_t, out);
}

// round 9
// speedup vs baseline: 1.2435x; 1.0643x over previous
#include <cuda_runtime.h>
#include <math.h>
#include <stdint.h>

// ---- problem constants (fixed shapes) ----
#define T_TOK  4096     // B * Q_LEN tokens
#define HIDDEN 4096
#define NH     32
#define HD     128
#define B_SEQ  8
#define Q_LEN  512
#define BS_PG  64       // paged-cache block size
#define NBLK   16

#define MAT_ELEMS ((size_t)4096 * 4096)

// ---- scratch (device globals; allocation-free) ----
__device__ float g_q[MAT_ELEMS];
__device__ float g_k[MAT_ELEMS];
__device__ float g_v[MAT_ELEMS];
__device__ float g_attn[MAT_ELEMS];   // written tf32-rounded by attn kernel
// tf32-pre-rounded GEMM operands
__device__ float g_hid_t[MAT_ELEMS];
__device__ float g_wq_t[MAT_ELEMS];
__device__ float g_wk_t[MAT_ELEMS];
__device__ float g_wv_t[MAT_ELEMS];
__device__ float g_wo_t[MAT_ELEMS];

// ---- helpers ----
__device__ __forceinline__ uint32_t smem_u32(const void* p) {
  return (uint32_t)__cvta_generic_to_shared(p);
}
__device__ __forceinline__ void cp_async16(uint32_t dst, const void* src) {
  asm volatile("cp.async.cg.shared.global [%0], [%1], 16;\n" ::"r"(dst), "l"(src));
}
__device__ __forceinline__ float f2tf_f(float x) {
  uint32_t u;
  asm("cvt.rna.tf32.f32 %0, %1;\n" : "=r"(u) : "f"(x));
  return __uint_as_float(u);
}
__device__ __forceinline__ void mma_tf32(float& d0, float& d1, float& d2, float& d3,
                                         uint32_t a0, uint32_t a1, uint32_t a2, uint32_t a3,
                                         uint32_t b0, uint32_t b1) {
  asm volatile(
      "mma.sync.aligned.m16n8k8.row.col.f32.tf32.tf32.f32 "
      "{%0,%1,%2,%3},{%4,%5,%6,%7},{%8,%9},{%0,%1,%2,%3};\n"
      : "+f"(d0), "+f"(d1), "+f"(d2), "+f"(d3)
      : "r"(a0), "r"(a1), "r"(a2), "r"(a3), "r"(b0), "r"(b1));
}

// ============================================================================
// Convert fp32 -> tf32 (rna), stored as float bits. Vectorized.
// ============================================================================
__global__ __launch_bounds__(256) void cvt_tf32_kernel(const float4* __restrict__ in,
                                                       float4* __restrict__ out) {
  size_t i = (size_t)blockIdx.x * 256 + threadIdx.x;
  if (i >= MAT_ELEMS / 4) return;
  float4 v = in[i];
  v.x = f2tf_f(v.x); v.y = f2tf_f(v.y); v.z = f2tf_f(v.z); v.w = f2tf_f(v.w);
  out[i] = v;
}

// ============================================================================
// TF32 tensor-core GEMM: C = A @ B, operands PRE-ROUNDED to tf32.
// CTA tile 128x128, BK=16, 4-stage cp.async, 256 threads, 2 CTAs/SM.
// ============================================================================
#define GBM 128
#define GBN 128
#define GBK 16
#define GSTAGES 4
#define GLDA 20
#define GLDB 136
#define AS_STAGE (GBM * GLDA)         // 2560 floats
#define BS_STAGE (GBK * GLDB)         // 2176 floats
#define STAGE_FLOATS (AS_STAGE + BS_STAGE)            // 4736
#define GEMM_SMEM_BYTES (STAGE_FLOATS * GSTAGES * 4)  // 75776 B

__device__ __forceinline__ void gemm_load_stage(
    float* smem, int s, int kt, int m0, int n0, int tid,
    const float* __restrict__ A, const float* __restrict__ B) {
  const int K = 4096, N = 4096;
  float* As = smem + s * STAGE_FLOATS;
  float* Bs = As + AS_STAGE;
  int k0 = kt * GBK;
#pragma unroll
  for (int i = 0; i < 2; i++) {
    int c = tid + i * 256;
    int r = c >> 2, kc = (c & 3) * 4;
    cp_async16(smem_u32(As + r * GLDA + kc),
               A + (size_t)(m0 + r) * K + k0 + kc);
  }
#pragma unroll
  for (int i = 0; i < 2; i++) {
    int c = tid + i * 256;
    int kr = c >> 5, nc = (c & 31) * 4;
    cp_async16(smem_u32(Bs + kr * GLDB + nc),
               B + (size_t)(k0 + kr) * N + n0 + nc);
  }
}

__global__ __launch_bounds__(256, 2) void gemm_tf32(
    const float* __restrict__ A, const float* __restrict__ B,
    float* __restrict__ C) {
  extern __shared__ float smem[];
  const int K = 4096, N = 4096;
  int tid = threadIdx.x;
  int m0 = blockIdx.y * GBM, n0 = blockIdx.x * GBN;
  int lane = tid & 31, warp = tid >> 5;
  int g = lane >> 2, t = lane & 3;
  int wm = (warp & 1) * 64;
  int wn = (warp >> 1) * 32;

  float acc[4][4][4];
#pragma unroll
  for (int mi = 0; mi < 4; mi++)
#pragma unroll
    for (int ni = 0; ni < 4; ni++)
#pragma unroll
      for (int e = 0; e < 4; e++) acc[mi][ni][e] = 0.f;

  const int NT = K / GBK;  // 256
#pragma unroll
  for (int s = 0; s < GSTAGES - 1; s++) {
    gemm_load_stage(smem, s, s, m0, n0, tid, A, B);
    asm volatile("cp.async.commit_group;\n");
  }

  for (int kt = 0; kt < NT; kt++) {
    asm volatile("cp.async.wait_group %0;\n" ::"n"(GSTAGES - 2));
    __syncthreads();
    int pf = kt + GSTAGES - 1;
    if (pf < NT) gemm_load_stage(smem, pf % GSTAGES, pf, m0, n0, tid, A, B);
    asm volatile("cp.async.commit_group;\n");

    const float* As = smem + (kt % GSTAGES) * STAGE_FLOATS;
    const float* Bs = As + AS_STAGE;
#pragma unroll
    for (int kk = 0; kk < GBK; kk += 8) {
      uint32_t a[4][4], b[4][2];
#pragma unroll
      for (int mi = 0; mi < 4; mi++) {
        int r = wm + mi * 16 + g;
        a[mi][0] = __float_as_uint(As[r * GLDA + kk + t]);
        a[mi][1] = __float_as_uint(As[(r + 8) * GLDA + kk + t]);
        a[mi][2] = __float_as_uint(As[r * GLDA + kk + t + 4]);
        a[mi][3] = __float_as_uint(As[(r + 8) * GLDA + kk + t + 4]);
      }
#pragma unroll
      for (int ni = 0; ni < 4; ni++) {
        int c = wn + ni * 8 + g;
        b[ni][0] = __float_as_uint(Bs[(kk + t) * GLDB + c]);
        b[ni][1] = __float_as_uint(Bs[(kk + t + 4) * GLDB + c]);
      }
#pragma unroll
      for (int mi = 0; mi < 4; mi++)
#pragma unroll
        for (int ni = 0; ni < 4; ni++)
          mma_tf32(acc[mi][ni][0], acc[mi][ni][1], acc[mi][ni][2], acc[mi][ni][3],
                   a[mi][0], a[mi][1], a[mi][2], a[mi][3],
                   b[ni][0], b[ni][1]);
    }
  }

#pragma unroll
  for (int mi = 0; mi < 4; mi++) {
#pragma unroll
    for (int ni = 0; ni < 4; ni++) {
      int r = m0 + wm + mi * 16 + g;
      int c = n0 + wn + ni * 8 + 2 * t;
      *(float2*)(C + (size_t)r * N + c) =
          make_float2(acc[mi][ni][0], acc[mi][ni][1]);
      *(float2*)(C + (size_t)(r + 8) * N + c) =
          make_float2(acc[mi][ni][2], acc[mi][ni][3]);
    }
  }
}

// ============================================================================
// RoPE (in-place on g_q, g_k).
// ============================================================================
__global__ void rope_kernel(float* __restrict__ q, float* __restrict__ k,
                            const int* __restrict__ pos_ids) {
  int idx = blockIdx.x * 256 + threadIdx.x;
  if (idx >= T_TOK * NH * 64) return;
  int j = idx & 63;
  int th = idx >> 6;
  int t = th >> 5;
  float pos = (float)pos_ids[t];
  float inv = expf(-logf(10000.f) * (float)(2 * j) * (1.f / 128.f));
  float ang = pos * inv;
  float s, c;
  sincosf(ang, &s, &c);
  size_t base = (size_t)th * 128;
  float q1 = q[base + j], q2 = q[base + j + 64];
  q[base + j]      = q1 * c - q2 * s;
  q[base + j + 64] = q2 * c + q1 * s;
  float k1 = k[base + j], k2 = k[base + j + 64];
  k[base + j]      = k1 * c - k2 * s;
  k[base + j + 64] = k2 * c + k1 * s;
}

// ============================================================================
// Flash attention, fp32. CTA = (q-tile 128, head, seq), 512 threads
// (16 warps = 4/SMSP for latency hiding). KV tile 128 (2 cache pages).
// Thread grid 32(q) x 16(kv/d), micro-tile 4x8. S staged via K smem region.
// QK column ownership interleaved (c = tc + 16j). Softmax state in regs,
// 16-lane (half-warp) shfl reductions.
// ============================================================================
#define ALDQ 132
#define ALDK 132                         // also S stride
#define ALDV 128
#define AOFF_K (128 * ALDQ)              // 16896
#define AOFF_V (AOFF_K + 128 * ALDK)     // 33792
#define AOFF_P (AOFF_V + 128 * ALDV)     // 50176
#define ATTN_SMEM_FLOATS (AOFF_P + 128)  // 50304 -> 201216 B

__global__ __launch_bounds__(512, 1) void attn_kernel(
    const float* __restrict__ k_cache, const float* __restrict__ v_cache,
    const int* __restrict__ block_tab, const int* __restrict__ pos_ids,
    const int* __restrict__ kv_len) {
  extern __shared__ float sm[];
  float* Qs = sm;
  float* Ks = sm + AOFF_K;   // aliased by S after QK
  float* Vs = sm + AOFF_V;
  int* Ps = (int*)(sm + AOFF_P);

  int qt = blockIdx.x, h = blockIdx.y, b = blockIdx.z;
  int tid = threadIdx.x;
  int tr = tid >> 4, tc = tid & 15;   // 32 x 16
  int t_base = b * Q_LEN + qt * 128;

  // ---- Q tile [128 x 128] ----
  for (int i = tid; i < 128 * 32; i += 512) {
    int r = i >> 5, d4 = (i & 31) * 4;
    float4 v = *(const float4*)(g_q + (size_t)(t_base + r) * HIDDEN + h * HD + d4);
    *(float4*)(&Qs[r * ALDQ + d4]) = v;
  }
  if (tid < 128) Ps[tid] = pos_ids[t_base + tid];
  __syncthreads();

  int kvl = kv_len[b];
  int maxp = 0;
  for (int i = 0; i < 128; i++) maxp = max(maxp, Ps[i]);
  int nt = min(maxp / 128 + 1, (kvl + 127) / 128);
  if (nt > 8) nt = 8;

  float m[4], l[4], o[4][8];
#pragma unroll
  for (int i = 0; i < 4; i++) {
    m[i] = -1e30f;
    l[i] = 0.f;
#pragma unroll
    for (int j = 0; j < 8; j++) o[i][j] = 0.f;
  }

  const float scale = 0.08838834764831845f;  // 1/sqrt(128)
  int qp_[4];
#pragma unroll
  for (int i = 0; i < 4; i++) qp_[i] = Ps[tr * 4 + i];

  for (int kt = 0; kt < nt; kt++) {
    __syncthreads();  // prior PV readers of Ss/Vs done before overwrite

    // ---- load K/V tile [128 x 128] via cp.async ----
    int blk0 = 0, blk1 = 0;
    if (kt < 4) {
      blk0 = block_tab[b * NBLK + 2 * kt];
      blk1 = block_tab[b * NBLK + 2 * kt + 1];
    }
#pragma unroll
    for (int j = 0; j < 8; j++) {
      int i = tid + j * 512;
      int r = i >> 5, d4 = (i & 31) * 4;
      const float *kb, *vb;
      if (kt < 4) {
        int blk = (r < 64) ? blk0 : blk1;
        size_t off = ((size_t)(blk * BS_PG + (r & 63)) * NH + h) * HD + d4;
        kb = k_cache + off;
        vb = v_cache + off;
      } else {
        size_t off = (size_t)(b * Q_LEN + (kt - 4) * 128 + r) * HIDDEN + h * HD + d4;
        kb = g_k + off;
        vb = g_v + off;
      }
      cp_async16(smem_u32(Ks + r * ALDK + d4), kb);
      cp_async16(smem_u32(Vs + r * ALDV + d4), vb);
    }
    asm volatile("cp.async.commit_group;\n");
    asm volatile("cp.async.wait_group 0;\n");
    __syncthreads();

    // ---- S = Q K^T : rows tr*4+i, cols tc + 16j ----
    float s_[4][8];
#pragma unroll
    for (int i = 0; i < 4; i++)
#pragma unroll
      for (int j = 0; j < 8; j++) s_[i][j] = 0.f;
#pragma unroll 4
    for (int d = 0; d < 128; d += 2) {
      float2 qa[4], kb[8];
#pragma unroll
      for (int i = 0; i < 4; i++)
        qa[i] = *(const float2*)(&Qs[(tr * 4 + i) * ALDQ + d]);
#pragma unroll
      for (int j = 0; j < 8; j++)
        kb[j] = *(const float2*)(&Ks[(tc + 16 * j) * ALDK + d]);
#pragma unroll
      for (int i = 0; i < 4; i++)
#pragma unroll
        for (int j = 0; j < 8; j++) {
          s_[i][j] = fmaf(qa[i].x, kb[j].x, s_[i][j]);
          s_[i][j] = fmaf(qa[i].y, kb[j].y, s_[i][j]);
        }
    }
    __syncthreads();  // all K reads done; Ks region now reusable for S

    // ---- mask + online softmax (registers + half-warp shfl) ----
#pragma unroll
    for (int i = 0; i < 4; i++) {
      int qp = qp_[i];
      float rmax = -1e30f;
#pragma unroll
      for (int j = 0; j < 8; j++) {
        int kvp = kt * 128 + tc + 16 * j;
        float sv = s_[i][j] * scale;
        if (kvp > qp || kvp >= kvl) sv = -1e30f;
        s_[i][j] = sv;
        rmax = fmaxf(rmax, sv);
      }
      rmax = fmaxf(rmax, __shfl_xor_sync(0xffffffffu, rmax, 1));
      rmax = fmaxf(rmax, __shfl_xor_sync(0xffffffffu, rmax, 2));
      rmax = fmaxf(rmax, __shfl_xor_sync(0xffffffffu, rmax, 4));
      rmax = fmaxf(rmax, __shfl_xor_sync(0xffffffffu, rmax, 8));
      float mnew = fmaxf(m[i], rmax);
      float sum = 0.f;
#pragma unroll
      for (int j = 0; j < 8; j++) {
        float p = __expf(s_[i][j] - mnew);
        s_[i][j] = p;
        sum += p;
      }
      sum += __shfl_xor_sync(0xffffffffu, sum, 1);
      sum += __shfl_xor_sync(0xffffffffu, sum, 2);
      sum += __shfl_xor_sync(0xffffffffu, sum, 4);
      sum += __shfl_xor_sync(0xffffffffu, sum, 8);
      float alpha = __expf(m[i] - mnew);
      m[i] = mnew;
      l[i] = l[i] * alpha + sum;
#pragma unroll
      for (int j = 0; j < 8; j++) o[i][j] *= alpha;
    }

    // ---- stage P into smem (K region) ----
    float* Ss = Ks;
#pragma unroll
    for (int i = 0; i < 4; i++)
#pragma unroll
      for (int j = 0; j < 8; j++)
        Ss[(tr * 4 + i) * ALDK + tc + 16 * j] = s_[i][j];
    __syncthreads();

    // ---- O += P @ V : O rows tr*4+i, cols tc*8..+7 ----
#pragma unroll 2
    for (int kk = 0; kk < 128; kk++) {
      float rp[4];
#pragma unroll
      for (int i = 0; i < 4; i++) rp[i] = Ss[(tr * 4 + i) * ALDK + kk];
      float4 v0 = *(const float4*)(&Vs[kk * ALDV + tc * 8]);
      float4 v1 = *(const float4*)(&Vs[kk * ALDV + tc * 8 + 4]);
#pragma unroll
      for (int i = 0; i < 4; i++) {
        o[i][0] = fmaf(rp[i], v0.x, o[i][0]);
        o[i][1] = fmaf(rp[i], v0.y, o[i][1]);
        o[i][2] = fmaf(rp[i], v0.z, o[i][2]);
        o[i][3] = fmaf(rp[i], v0.w, o[i][3]);
        o[i][4] = fmaf(rp[i], v1.x, o[i][4]);
        o[i][5] = fmaf(rp[i], v1.y, o[i][5]);
        o[i][6] = fmaf(rp[i], v1.z, o[i][6]);
        o[i][7] = fmaf(rp[i], v1.w, o[i][7]);
      }
    }
  }

  // ---- normalize + tf32-round + write ----
#pragma unroll
  for (int i = 0; i < 4; i++) {
    int r = tr * 4 + i;
    float inv_l = 1.f / l[i];
    float* dst = g_attn + (size_t)(t_base + r) * HIDDEN + h * HD + tc * 8;
    float4 o0 = make_float4(f2tf_f(o[i][0] * inv_l), f2tf_f(o[i][1] * inv_l),
                            f2tf_f(o[i][2] * inv_l), f2tf_f(o[i][3] * inv_l));
    float4 o1 = make_float4(f2tf_f(o[i][4] * inv_l), f2tf_f(o[i][5] * inv_l),
                            f2tf_f(o[i][6] * inv_l), f2tf_f(o[i][7] * inv_l));
    *(float4*)(dst) = o0;
    *(float4*)(dst + 4) = o1;
  }
}

// ============================================================================
extern "C" void kernel_launch(void* const* d_in, const int* in_sizes, int n_in,
                              void* d_out, int out_size) {
  const float* hidden = (const float*)d_in[0];
  const float* Wq = (const float*)d_in[1];
  const float* Wk = (const float*)d_in[2];
  const float* Wv = (const float*)d_in[3];
  const float* Wo = (const float*)d_in[4];
  const float* kc = (const float*)d_in[5];
  const float* vc = (const float*)d_in[6];
  const int* btab = (const int*)d_in[7];
  const int* pos = (const int*)d_in[8];
  const int* kvlen = (const int*)d_in[9];
  float* out = (float*)d_out;

  float *q, *k, *v, *attn, *hid_t, *wq_t, *wk_t, *wv_t, *wo_t;
  cudaGetSymbolAddress((void**)&q, g_q);
  cudaGetSymbolAddress((void**)&k, g_k);
  cudaGetSymbolAddress((void**)&v, g_v);
  cudaGetSymbolAddress((void**)&attn, g_attn);
  cudaGetSymbolAddress((void**)&hid_t, g_hid_t);
  cudaGetSymbolAddress((void**)&wq_t, g_wq_t);
  cudaGetSymbolAddress((void**)&wk_t, g_wk_t);
  cudaGetSymbolAddress((void**)&wv_t, g_wv_t);
  cudaGetSymbolAddress((void**)&wo_t, g_wo_t);

  // pre-round GEMM operands to tf32
  int cvt_grid = (int)((MAT_ELEMS / 4 + 255) / 256);
  cvt_tf32_kernel<<<cvt_grid, 256>>>((const float4*)hidden, (float4*)hid_t);
  cvt_tf32_kernel<<<cvt_grid, 256>>>((const float4*)Wq, (float4*)wq_t);
  cvt_tf32_kernel<<<cvt_grid, 256>>>((const float4*)Wk, (float4*)wk_t);
  cvt_tf32_kernel<<<cvt_grid, 256>>>((const float4*)Wv, (float4*)wv_t);
  cvt_tf32_kernel<<<cvt_grid, 256>>>((const float4*)Wo, (float4*)wo_t);

  cudaFuncSetAttribute(gemm_tf32, cudaFuncAttributeMaxDynamicSharedMemorySize,
                       GEMM_SMEM_BYTES);
  dim3 gg(32, 32);  // N/128, M/128
  gemm_tf32<<<gg, 256, GEMM_SMEM_BYTES>>>(hid_t, wq_t, q);
  gemm_tf32<<<gg, 256, GEMM_SMEM_BYTES>>>(hid_t, wk_t, k);
  gemm_tf32<<<gg, 256, GEMM_SMEM_BYTES>>>(hid_t, wv_t, v);

  rope_kernel<<<(T_TOK * NH * 64 + 255) / 256, 256>>>(q, k, pos);

  cudaFuncSetAttribute(attn_kernel, cudaFuncAttributeMaxDynamicSharedMemorySize,
                       ATTN_SMEM_FLOATS * 4);
  dim3 ga(4, NH, B_SEQ);  // (q-tile of 128, head, seq)
  attn_kernel<<<ga, 512, ATTN_SMEM_FLOATS * 4>>>(kc, vc, btab, pos, kvlen);

  gemm_tf32<<<gg, 256, GEMM_SMEM_BYTES>>>(attn, wo_t, out);
}

// round 10
// speedup vs baseline: 1.3921x; 1.1195x over previous
#include <cuda_runtime.h>
#include <math.h>
#include <stdint.h>

// ---- problem constants (fixed shapes) ----
#define T_TOK  4096     // B * Q_LEN tokens
#define HIDDEN 4096
#define NH     32
#define HD     128
#define B_SEQ  8
#define Q_LEN  512
#define BS_PG  64       // paged-cache block size
#define NBLK   16

#define MAT_ELEMS ((size_t)4096 * 4096)

// ---- scratch (device globals; allocation-free) ----
__device__ float g_q[MAT_ELEMS];
__device__ float g_k[MAT_ELEMS];
__device__ float g_v[MAT_ELEMS];
__device__ float g_attn[MAT_ELEMS];   // written tf32-rounded by attn kernel
// tf32-pre-rounded GEMM operands
__device__ float g_hid_t[MAT_ELEMS];
__device__ float g_wq_t[MAT_ELEMS];
__device__ float g_wk_t[MAT_ELEMS];
__device__ float g_wv_t[MAT_ELEMS];
__device__ float g_wo_t[MAT_ELEMS];

// ---- helpers ----
__device__ __forceinline__ uint32_t smem_u32(const void* p) {
  return (uint32_t)__cvta_generic_to_shared(p);
}
__device__ __forceinline__ void cp_async16(uint32_t dst, const void* src) {
  asm volatile("cp.async.cg.shared.global [%0], [%1], 16;\n" ::"r"(dst), "l"(src));
}
__device__ __forceinline__ float f2tf_f(float x) {
  uint32_t u;
  asm("cvt.rna.tf32.f32 %0, %1;\n" : "=r"(u) : "f"(x));
  return __uint_as_float(u);
}
// split fp32 -> (hi, lo) tf32 pair; hi+lo == x to ~2^-22 rel
__device__ __forceinline__ void split_tf32(float x, uint32_t& hi, uint32_t& lo) {
  float h = f2tf_f(x);
  hi = __float_as_uint(h);
  lo = __float_as_uint(f2tf_f(x - h));
}
__device__ __forceinline__ void mma_tf32(float& d0, float& d1, float& d2, float& d3,
                                         uint32_t a0, uint32_t a1, uint32_t a2, uint32_t a3,
                                         uint32_t b0, uint32_t b1) {
  asm volatile(
      "mma.sync.aligned.m16n8k8.row.col.f32.tf32.tf32.f32 "
      "{%0,%1,%2,%3},{%4,%5,%6,%7},{%8,%9},{%0,%1,%2,%3};\n"
      : "+f"(d0), "+f"(d1), "+f"(d2), "+f"(d3)
      : "r"(a0), "r"(a1), "r"(a2), "r"(a3), "r"(b0), "r"(b1));
}

// ============================================================================
// Convert fp32 -> tf32 (rna), stored as float bits. Vectorized.
// ============================================================================
__global__ __launch_bounds__(256) void cvt_tf32_kernel(const float4* __restrict__ in,
                                                       float4* __restrict__ out) {
  size_t i = (size_t)blockIdx.x * 256 + threadIdx.x;
  if (i >= MAT_ELEMS / 4) return;
  float4 v = in[i];
  v.x = f2tf_f(v.x); v.y = f2tf_f(v.y); v.z = f2tf_f(v.z); v.w = f2tf_f(v.w);
  out[i] = v;
}

// ============================================================================
// TF32 tensor-core GEMM: C = A @ B, operands PRE-ROUNDED to tf32.
// CTA tile 128x128, BK=16, 4-stage cp.async, 256 threads, 2 CTAs/SM.
// ============================================================================
#define GBM 128
#define GBN 128
#define GBK 16
#define GSTAGES 4
#define GLDA 20
#define GLDB 136
#define AS_STAGE (GBM * GLDA)         // 2560 floats
#define BS_STAGE (GBK * GLDB)         // 2176 floats
#define STAGE_FLOATS (AS_STAGE + BS_STAGE)            // 4736
#define GEMM_SMEM_BYTES (STAGE_FLOATS * GSTAGES * 4)  // 75776 B

__device__ __forceinline__ void gemm_load_stage(
    float* smem, int s, int kt, int m0, int n0, int tid,
    const float* __restrict__ A, const float* __restrict__ B) {
  const int K = 4096, N = 4096;
  float* As = smem + s * STAGE_FLOATS;
  float* Bs = As + AS_STAGE;
  int k0 = kt * GBK;
#pragma unroll
  for (int i = 0; i < 2; i++) {
    int c = tid + i * 256;
    int r = c >> 2, kc = (c & 3) * 4;
    cp_async16(smem_u32(As + r * GLDA + kc),
               A + (size_t)(m0 + r) * K + k0 + kc);
  }
#pragma unroll
  for (int i = 0; i < 2; i++) {
    int c = tid + i * 256;
    int kr = c >> 5, nc = (c & 31) * 4;
    cp_async16(smem_u32(Bs + kr * GLDB + nc),
               B + (size_t)(k0 + kr) * N + n0 + nc);
  }
}

__global__ __launch_bounds__(256, 2) void gemm_tf32(
    const float* __restrict__ A, const float* __restrict__ B,
    float* __restrict__ C) {
  extern __shared__ float smem[];
  const int K = 4096, N = 4096;
  int tid = threadIdx.x;
  int m0 = blockIdx.y * GBM, n0 = blockIdx.x * GBN;
  int lane = tid & 31, warp = tid >> 5;
  int g = lane >> 2, t = lane & 3;
  int wm = (warp & 1) * 64;
  int wn = (warp >> 1) * 32;

  float acc[4][4][4];
#pragma unroll
  for (int mi = 0; mi < 4; mi++)
#pragma unroll
    for (int ni = 0; ni < 4; ni++)
#pragma unroll
      for (int e = 0; e < 4; e++) acc[mi][ni][e] = 0.f;

  const int NT = K / GBK;  // 256
#pragma unroll
  for (int s = 0; s < GSTAGES - 1; s++) {
    gemm_load_stage(smem, s, s, m0, n0, tid, A, B);
    asm volatile("cp.async.commit_group;\n");
  }

  for (int kt = 0; kt < NT; kt++) {
    asm volatile("cp.async.wait_group %0;\n" ::"n"(GSTAGES - 2));
    __syncthreads();
    int pf = kt + GSTAGES - 1;
    if (pf < NT) gemm_load_stage(smem, pf % GSTAGES, pf, m0, n0, tid, A, B);
    asm volatile("cp.async.commit_group;\n");

    const float* As = smem + (kt % GSTAGES) * STAGE_FLOATS;
    const float* Bs = As + AS_STAGE;
#pragma unroll
    for (int kk = 0; kk < GBK; kk += 8) {
      uint32_t a[4][4], b[4][2];
#pragma unroll
      for (int mi = 0; mi < 4; mi++) {
        int r = wm + mi * 16 + g;
        a[mi][0] = __float_as_uint(As[r * GLDA + kk + t]);
        a[mi][1] = __float_as_uint(As[(r + 8) * GLDA + kk + t]);
        a[mi][2] = __float_as_uint(As[r * GLDA + kk + t + 4]);
        a[mi][3] = __float_as_uint(As[(r + 8) * GLDA + kk + t + 4]);
      }
#pragma unroll
      for (int ni = 0; ni < 4; ni++) {
        int c = wn + ni * 8 + g;
        b[ni][0] = __float_as_uint(Bs[(kk + t) * GLDB + c]);
        b[ni][1] = __float_as_uint(Bs[(kk + t + 4) * GLDB + c]);
      }
#pragma unroll
      for (int mi = 0; mi < 4; mi++)
#pragma unroll
        for (int ni = 0; ni < 4; ni++)
          mma_tf32(acc[mi][ni][0], acc[mi][ni][1], acc[mi][ni][2], acc[mi][ni][3],
                   a[mi][0], a[mi][1], a[mi][2], a[mi][3],
                   b[ni][0], b[ni][1]);
    }
  }

#pragma unroll
  for (int mi = 0; mi < 4; mi++) {
#pragma unroll
    for (int ni = 0; ni < 4; ni++) {
      int r = m0 + wm + mi * 16 + g;
      int c = n0 + wn + ni * 8 + 2 * t;
      *(float2*)(C + (size_t)r * N + c) =
          make_float2(acc[mi][ni][0], acc[mi][ni][1]);
      *(float2*)(C + (size_t)(r + 8) * N + c) =
          make_float2(acc[mi][ni][2], acc[mi][ni][3]);
    }
  }
}

// ============================================================================
// RoPE (in-place on g_q, g_k).
// ============================================================================
__global__ void rope_kernel(float* __restrict__ q, float* __restrict__ k,
                            const int* __restrict__ pos_ids) {
  int idx = blockIdx.x * 256 + threadIdx.x;
  if (idx >= T_TOK * NH * 64) return;
  int j = idx & 63;
  int th = idx >> 6;
  int t = th >> 5;
  float pos = (float)pos_ids[t];
  float inv = expf(-logf(10000.f) * (float)(2 * j) * (1.f / 128.f));
  float ang = pos * inv;
  float s, c;
  sincosf(ang, &s, &c);
  size_t base = (size_t)th * 128;
  float q1 = q[base + j], q2 = q[base + j + 64];
  q[base + j]      = q1 * c - q2 * s;
  q[base + j + 64] = q2 * c + q1 * s;
  float k1 = k[base + j], k2 = k[base + j + 64];
  k[base + j]      = k1 * c - k2 * s;
  k[base + j + 64] = k2 * c + k1 * s;
}

// ============================================================================
// Flash attention with SPLIT-TF32 tensor-core matmuls (fp32-equivalent).
// CTA = (q-tile 128, head, seq), 512 threads = 16 warps, warp grid 4m x 4n,
// warp tiles 32x32. QK and PV each: 3 mma passes (hi*hi + hi*lo + lo*hi),
// operands split in registers from fp32 smem tiles. S staged via K region.
// Online softmax state (M,L,alpha) in smem, 4 threads/row.
// ============================================================================
#define ALDQ 132
#define ALDK 132                         // K tile stride; also S stride
#define ALDV 136                         // conflict-free for PV B-frag loads
#define AOFF_K (128 * ALDQ)              // 16896
#define AOFF_V (AOFF_K + 128 * ALDK)     // 33792
#define AOFF_M (AOFF_V + 128 * ALDV)     // 51200
#define AOFF_L (AOFF_M + 128)
#define AOFF_A (AOFF_L + 128)
#define AOFF_P (AOFF_A + 128)
#define ATTN_SMEM_FLOATS (AOFF_P + 128)  // 51712 -> 206848 B

__global__ __launch_bounds__(512, 1) void attn_kernel(
    const float* __restrict__ k_cache, const float* __restrict__ v_cache,
    const int* __restrict__ block_tab, const int* __restrict__ pos_ids,
    const int* __restrict__ kv_len) {
  extern __shared__ float sm[];
  float* Qs = sm;
  float* Ks = sm + AOFF_K;   // aliased by S after QK
  float* Vs = sm + AOFF_V;
  float* Ms = sm + AOFF_M;
  float* Ls = sm + AOFF_L;
  float* Al = sm + AOFF_A;
  int* Ps = (int*)(sm + AOFF_P);
  float* Ss = Ks;            // S tile aliases K tile

  int qt = blockIdx.x, h = blockIdx.y, b = blockIdx.z;
  int tid = threadIdx.x;
  int lane = tid & 31, warp = tid >> 5;
  int g = lane >> 2, t = lane & 3;
  int wm = (warp >> 2) * 32;   // 4 warps over 128 q-rows
  int wn = (warp & 3) * 32;    // 4 warps over 128 kv-cols (QK) / d-cols (PV)
  int t_base = b * Q_LEN + qt * 128;

  // ---- Q tile [128 x 128] + softmax state init ----
  for (int i = tid; i < 128 * 32; i += 512) {
    int r = i >> 5, d4 = (i & 31) * 4;
    float4 v = *(const float4*)(g_q + (size_t)(t_base + r) * HIDDEN + h * HD + d4);
    *(float4*)(&Qs[r * ALDQ + d4]) = v;
  }
  if (tid < 128) {
    Ps[tid] = pos_ids[t_base + tid];
    Ms[tid] = -1e30f;
    Ls[tid] = 0.f;
  }
  __syncthreads();

  int kvl = kv_len[b];
  int maxp = 0;
  for (int i = 0; i < 128; i++) maxp = max(maxp, Ps[i]);
  int nt = min(maxp / 128 + 1, (kvl + 127) / 128);
  if (nt > 8) nt = 8;

  float o[2][4][4];
#pragma unroll
  for (int mi = 0; mi < 2; mi++)
#pragma unroll
    for (int ni = 0; ni < 4; ni++)
#pragma unroll
      for (int e = 0; e < 4; e++) o[mi][ni][e] = 0.f;

  const float scale = 0.08838834764831845f;  // 1/sqrt(128)

  for (int kt = 0; kt < nt; kt++) {
    __syncthreads();  // prior tile's Ss/Vs readers done before overwrite

    // ---- load K/V tile [128 x 128] via cp.async ----
    int blk0 = 0, blk1 = 0;
    if (kt < 4) {
      blk0 = block_tab[b * NBLK + 2 * kt];
      blk1 = block_tab[b * NBLK + 2 * kt + 1];
    }
#pragma unroll
    for (int j = 0; j < 8; j++) {
      int i = tid + j * 512;
      int r = i >> 5, d4 = (i & 31) * 4;
      const float *kb, *vb;
      if (kt < 4) {
        int blk = (r < 64) ? blk0 : blk1;
        size_t off = ((size_t)(blk * BS_PG + (r & 63)) * NH + h) * HD + d4;
        kb = k_cache + off;
        vb = v_cache + off;
      } else {
        size_t off = (size_t)(b * Q_LEN + (kt - 4) * 128 + r) * HIDDEN + h * HD + d4;
        kb = g_k + off;
        vb = g_v + off;
      }
      cp_async16(smem_u32(Ks + r * ALDK + d4), kb);
      cp_async16(smem_u32(Vs + r * ALDV + d4), vb);
    }
    asm volatile("cp.async.commit_group;\n");
    asm volatile("cp.async.wait_group 0;\n");
    __syncthreads();

    // ---- S = Q K^T via split-tf32 mma (warp tile 32x32) ----
    float s_[2][4][4];
#pragma unroll
    for (int mi = 0; mi < 2; mi++)
#pragma unroll
      for (int ni = 0; ni < 4; ni++)
#pragma unroll
        for (int e = 0; e < 4; e++) s_[mi][ni][e] = 0.f;

#pragma unroll
    for (int kk = 0; kk < 128; kk += 8) {
      uint32_t ah[2][4], al[2][4], bh[4][2], bl[4][2];
#pragma unroll
      for (int mi = 0; mi < 2; mi++) {
        int r = wm + mi * 16 + g;
        split_tf32(Qs[r * ALDQ + kk + t],           ah[mi][0], al[mi][0]);
        split_tf32(Qs[(r + 8) * ALDQ + kk + t],     ah[mi][1], al[mi][1]);
        split_tf32(Qs[r * ALDQ + kk + t + 4],       ah[mi][2], al[mi][2]);
        split_tf32(Qs[(r + 8) * ALDQ + kk + t + 4], ah[mi][3], al[mi][3]);
      }
#pragma unroll
      for (int ni = 0; ni < 4; ni++) {
        int c = wn + ni * 8 + g;
        split_tf32(Ks[c * ALDK + kk + t],     bh[ni][0], bl[ni][0]);
        split_tf32(Ks[c * ALDK + kk + t + 4], bh[ni][1], bl[ni][1]);
      }
#pragma unroll
      for (int mi = 0; mi < 2; mi++)
#pragma unroll
        for (int ni = 0; ni < 4; ni++) {
          mma_tf32(s_[mi][ni][0], s_[mi][ni][1], s_[mi][ni][2], s_[mi][ni][3],
                   ah[mi][0], ah[mi][1], ah[mi][2], ah[mi][3],
                   bh[ni][0], bh[ni][1]);
          mma_tf32(s_[mi][ni][0], s_[mi][ni][1], s_[mi][ni][2], s_[mi][ni][3],
                   ah[mi][0], ah[mi][1], ah[mi][2], ah[mi][3],
                   bl[ni][0], bl[ni][1]);
          mma_tf32(s_[mi][ni][0], s_[mi][ni][1], s_[mi][ni][2], s_[mi][ni][3],
                   al[mi][0], al[mi][1], al[mi][2], al[mi][3],
                   bh[ni][0], bh[ni][1]);
        }
    }
    __syncthreads();  // all K frag reads done; Ks region reusable for S

    // ---- scale + mask + stage S to smem (K region) ----
#pragma unroll
    for (int mi = 0; mi < 2; mi++) {
      int r = wm + mi * 16 + g;
      int qp0 = Ps[r], qp1 = Ps[r + 8];
#pragma unroll
      for (int ni = 0; ni < 4; ni++) {
        int c = wn + ni * 8 + 2 * t;
        int kvp0 = kt * 128 + c, kvp1 = kvp0 + 1;
        float e0 = s_[mi][ni][0] * scale;
        float e1 = s_[mi][ni][1] * scale;
        float e2 = s_[mi][ni][2] * scale;
        float e3 = s_[mi][ni][3] * scale;
        if (kvp0 > qp0 || kvp0 >= kvl) e0 = -1e30f;
        if (kvp1 > qp0 || kvp1 >= kvl) e1 = -1e30f;
        if (kvp0 > qp1 || kvp0 >= kvl) e2 = -1e30f;
        if (kvp1 > qp1 || kvp1 >= kvl) e3 = -1e30f;
        *(float2*)(&Ss[r * ALDK + c]) = make_float2(e0, e1);
        *(float2*)(&Ss[(r + 8) * ALDK + c]) = make_float2(e2, e3);
      }
    }
    __syncthreads();

    // ---- online softmax: 4 threads per row, 32 cols each ----
    {
      int row = tid >> 2, seg = tid & 3;
      float* Sr = &Ss[row * ALDK + seg * 32];
      float vbuf[32];
      float mx = -1e30f;
#pragma unroll
      for (int i4 = 0; i4 < 8; i4++) {
        float4 vv = *(float4*)(&Sr[i4 * 4]);
        vbuf[i4 * 4 + 0] = vv.x; vbuf[i4 * 4 + 1] = vv.y;
        vbuf[i4 * 4 + 2] = vv.z; vbuf[i4 * 4 + 3] = vv.w;
        mx = fmaxf(mx, fmaxf(fmaxf(vv.x, vv.y), fmaxf(vv.z, vv.w)));
      }
      mx = fmaxf(mx, __shfl_xor_sync(0xffffffffu, mx, 1));
      mx = fmaxf(mx, __shfl_xor_sync(0xffffffffu, mx, 2));
      float m_old = Ms[row];
      float m_new = fmaxf(m_old, mx);
      float sum = 0.f;
#pragma unroll
      for (int i = 0; i < 32; i++) {
        float p = __expf(vbuf[i] - m_new);
        vbuf[i] = p;
        sum += p;
      }
#pragma unroll
      for (int i4 = 0; i4 < 8; i4++)
        *(float4*)(&Sr[i4 * 4]) = make_float4(vbuf[i4 * 4], vbuf[i4 * 4 + 1],
                                              vbuf[i4 * 4 + 2], vbuf[i4 * 4 + 3]);
      sum += __shfl_xor_sync(0xffffffffu, sum, 1);
      sum += __shfl_xor_sync(0xffffffffu, sum, 2);
      if (seg == 0) {
        float alpha = __expf(m_old - m_new);
        Al[row] = alpha;
        Ls[row] = Ls[row] * alpha + sum;
        Ms[row] = m_new;
      }
    }
    __syncthreads();

    // ---- rescale O by alpha, then O += P @ V via split-tf32 mma ----
#pragma unroll
    for (int mi = 0; mi < 2; mi++) {
      int r = wm + mi * 16 + g;
      float a0 = Al[r], a1 = Al[r + 8];
#pragma unroll
      for (int ni = 0; ni < 4; ni++) {
        o[mi][ni][0] *= a0; o[mi][ni][1] *= a0;
        o[mi][ni][2] *= a1; o[mi][ni][3] *= a1;
      }
    }
#pragma unroll
    for (int kk = 0; kk < 128; kk += 8) {
      uint32_t ah[2][4], al[2][4], bh[4][2], bl[4][2];
#pragma unroll
      for (int mi = 0; mi < 2; mi++) {
        int r = wm + mi * 16 + g;
        split_tf32(Ss[r * ALDK + kk + t],           ah[mi][0], al[mi][0]);
        split_tf32(Ss[(r + 8) * ALDK + kk + t],     ah[mi][1], al[mi][1]);
        split_tf32(Ss[r * ALDK + kk + t + 4],       ah[mi][2], al[mi][2]);
        split_tf32(Ss[(r + 8) * ALDK + kk + t + 4], ah[mi][3], al[mi][3]);
      }
#pragma unroll
      for (int ni = 0; ni < 4; ni++) {
        int c = wn + ni * 8 + g;
        split_tf32(Vs[(kk + t) * ALDV + c],     bh[ni][0], bl[ni][0]);
        split_tf32(Vs[(kk + t + 4) * ALDV + c], bh[ni][1], bl[ni][1]);
      }
#pragma unroll
      for (int mi = 0; mi < 2; mi++)
#pragma unroll
        for (int ni = 0; ni < 4; ni++) {
          mma_tf32(o[mi][ni][0], o[mi][ni][1], o[mi][ni][2], o[mi][ni][3],
                   ah[mi][0], ah[mi][1], ah[mi][2], ah[mi][3],
                   bh[ni][0], bh[ni][1]);
          mma_tf32(o[mi][ni][0], o[mi][ni][1], o[mi][ni][2], o[mi][ni][3],
                   ah[mi][0], ah[mi][1], ah[mi][2], ah[mi][3],
                   bl[ni][0], bl[ni][1]);
          mma_tf32(o[mi][ni][0], o[mi][ni][1], o[mi][ni][2], o[mi][ni][3],
                   al[mi][0], al[mi][1], al[mi][2], al[mi][3],
                   bh[ni][0], bh[ni][1]);
        }
    }
  }

  // ---- normalize + tf32-round + write ----
#pragma unroll
  for (int mi = 0; mi < 2; mi++) {
    int r = wm + mi * 16 + g;
    float il0 = 1.f / Ls[r], il1 = 1.f / Ls[r + 8];
#pragma unroll
    for (int ni = 0; ni < 4; ni++) {
      int c = wn + ni * 8 + 2 * t;
      float* d0 = g_attn + (size_t)(t_base + r) * HIDDEN + h * HD + c;
      float* d1 = g_attn + (size_t)(t_base + r + 8) * HIDDEN + h * HD + c;
      *(float2*)d0 = make_float2(f2tf_f(o[mi][ni][0] * il0), f2tf_f(o[mi][ni][1] * il0));
      *(float2*)d1 = make_float2(f2tf_f(o[mi][ni][2] * il1), f2tf_f(o[mi][ni][3] * il1));
    }
  }
}

// ============================================================================
extern "C" void kernel_launch(void* const* d_in, const int* in_sizes, int n_in,
                              void* d_out, int out_size) {
  const float* hidden = (const float*)d_in[0];
  const float* Wq = (const float*)d_in[1];
  const float* Wk = (const float*)d_in[2];
  const float* Wv = (const float*)d_in[3];
  const float* Wo = (const float*)d_in[4];
  const float* kc = (const float*)d_in[5];
  const float* vc = (const float*)d_in[6];
  const int* btab = (const int*)d_in[7];
  const int* pos = (const int*)d_in[8];
  const int* kvlen = (const int*)d_in[9];
  float* out = (float*)d_out;

  float *q, *k, *v, *attn, *hid_t, *wq_t, *wk_t, *wv_t, *wo_t;
  cudaGetSymbolAddress((void**)&q, g_q);
  cudaGetSymbolAddress((void**)&k, g_k);
  cudaGetSymbolAddress((void**)&v, g_v);
  cudaGetSymbolAddress((void**)&attn, g_attn);
  cudaGetSymbolAddress((void**)&hid_t, g_hid_t);
  cudaGetSymbolAddress((void**)&wq_t, g_wq_t);
  cudaGetSymbolAddress((void**)&wk_t, g_wk_t);
  cudaGetSymbolAddress((void**)&wv_t, g_wv_t);
  cudaGetSymbolAddress((void**)&wo_t, g_wo_t);

  // pre-round GEMM operands to tf32
  int cvt_grid = (int)((MAT_ELEMS / 4 + 255) / 256);
  cvt_tf32_kernel<<<cvt_grid, 256>>>((const float4*)hidden, (float4*)hid_t);
  cvt_tf32_kernel<<<cvt_grid, 256>>>((const float4*)Wq, (float4*)wq_t);
  cvt_tf32_kernel<<<cvt_grid, 256>>>((const float4*)Wk, (float4*)wk_t);
  cvt_tf32_kernel<<<cvt_grid, 256>>>((const float4*)Wv, (float4*)wv_t);
  cvt_tf32_kernel<<<cvt_grid, 256>>>((const float4*)Wo, (float4*)wo_t);

  cudaFuncSetAttribute(gemm_tf32, cudaFuncAttributeMaxDynamicSharedMemorySize,
                       GEMM_SMEM_BYTES);
  dim3 gg(32, 32);  // N/128, M/128
  gemm_tf32<<<gg, 256, GEMM_SMEM_BYTES>>>(hid_t, wq_t, q);
  gemm_tf32<<<gg, 256, GEMM_SMEM_BYTES>>>(hid_t, wk_t, k);
  gemm_tf32<<<gg, 256, GEMM_SMEM_BYTES>>>(hid_t, wv_t, v);

  rope_kernel<<<(T_TOK * NH * 64 + 255) / 256, 256>>>(q, k, pos);

  cudaFuncSetAttribute(attn_kernel, cudaFuncAttributeMaxDynamicSharedMemorySize,
                       ATTN_SMEM_FLOATS * 4);
  dim3 ga(4, NH, B_SEQ);  // (q-tile of 128, head, seq)
  attn_kernel<<<ga, 512, ATTN_SMEM_FLOATS * 4>>>(kc, vc, btab, pos, kvlen);

  gemm_tf32<<<gg, 256, GEMM_SMEM_BYTES>>>(attn, wo_t, out);
}